// round 14
// baseline (speedup 1.0000x reference)
#include <cuda_runtime.h>
#include <cuda_bf16.h>

typedef unsigned long long ull;
typedef unsigned int u32;

// ---------------- problem constants (fixed shapes per reference) -------------
#define NMAX   50000
#define EMAX   1250000
#define GMAX   1024
#define LD     32      // label/embedding dim
#define HD     64      // hidden dim
#define NL     51      // number of labels (MAX_LABEL+1)
#define CW     32      // packed u16 count words per node (64 halves >= NL)
#define TP     68      // smem row pitch (floats) for 64-node tiles

// ---------------- device scratch (no allocation allowed) --------------------
__device__ u32   g_lcnt[NMAX * CW];  // per-node packed u16 label histograms
__device__ float g_EW  [NL * HD];    // emb @ W1_0  (51 x 64)
__device__ float g_h1 [NMAX * HD];   // layer0 output h
__device__ float g_ag1[NMAX * HD];   // layer1 aggregation
__device__ float g_sum[GMAX * HD];   // per-graph feature sums
__device__ float g_cnt[GMAX];        // per-graph node counts

// ---------------- packed f32x2 helpers (Blackwell FFMA2) --------------------
__device__ __forceinline__ void fma2(ull& acc, ull a, ull b) {
    asm("fma.rn.f32x2 %0, %1, %2, %0;" : "+l"(acc) : "l"(a), "l"(b));
}
__device__ __forceinline__ ull pack_dup(float x) {
    ull r;
    asm("mov.b64 %0, {%1, %1};" : "=l"(r) : "r"(__float_as_uint(x)));
    return r;
}
__device__ __forceinline__ float2 unpack2(ull v) {
    unsigned lo, hi;
    asm("mov.b64 {%0, %1}, %2;" : "=r"(lo), "=r"(hi) : "l"(v));
    return make_float2(__uint_as_float(lo), __uint_as_float(hi));
}

// ---------------- init: zero accumulators, seed self-label counts ------------
__global__ void init_kernel(const int* __restrict__ labels, int n, int g,
                            u32* __restrict__ lcnt,
                            float* __restrict__ ag1,
                            float* __restrict__ sums, float* __restrict__ cnts)
{
    int idx = blockIdx.x * blockDim.x + threadIdx.x;
    if (idx < n) {
        uint4 z = make_uint4(0, 0, 0, 0);
        uint4* p = reinterpret_cast<uint4*>(lcnt + (size_t)idx * CW);
#pragma unroll
        for (int w = 0; w < CW / 4; w++) p[w] = z;
        int lab = labels[idx];
        lab = lab < 0 ? 0 : (lab > NL - 1 ? NL - 1 : lab);
        lcnt[(size_t)idx * CW + (lab >> 1)] = 1u << ((lab & 1) * 16);
    }
    if (idx < n * HD) ag1[idx] = 0.f;
    if (idx < g * HD) sums[idx] = 0.f;
    if (idx < g)      cnts[idx] = 0.f;
}

// ---------------- EW = emb @ W1_0  (51 x 64, tiny) ---------------------------
__global__ void ew_kernel(const float* __restrict__ emb,
                          const float* __restrict__ W1,
                          float* __restrict__ EW)
{
    int idx = blockIdx.x * blockDim.x + threadIdx.x;
    if (idx >= NL * HD) return;
    int l = idx / HD, f = idx % HD;
    float s = 0.f;
#pragma unroll
    for (int k = 0; k < LD; k++) s += emb[l * LD + k] * W1[k * HD + f];
    EW[idx] = s;
}

// ---------------- layer0 edge pass: label histogram scatter ------------------
__global__ void __launch_bounds__(256)
label_scatter_kernel(const int* __restrict__ src, const int* __restrict__ dst,
                     const int* __restrict__ labels, u32* __restrict__ lcnt, int E)
{
    int e = blockIdx.x * blockDim.x + threadIdx.x;
    if (e >= E) return;
    int s = __ldg(&src[e]);
    int d = __ldg(&dst[e]);
    int lab = __ldg(&labels[s]);
    lab = lab < 0 ? 0 : (lab > NL - 1 ? NL - 1 : lab);
    atomicAdd(&lcnt[(size_t)d * CW + (lab >> 1)], 1u << ((lab & 1) * 16));
}

// ---------------- layer0 fused MLP from label counts (64-node tile) ----------
// phase 1: a = relu(b1 + cnt' @ EW)   phase 2: h1 = relu(a @ W2 + b2)
// 256 threads; thread = 2 nodes x 8 feats (8 packed f32x2 accumulators).
// Single aliased smem buffer buf[64][TP]: counts then intermediate As.
__global__ void __launch_bounds__(256, 5)
mlp0_kernel(const u32* __restrict__ lcnt,
            const float* __restrict__ EW, const float* __restrict__ b1,
            const float* __restrict__ W2, const float* __restrict__ b2,
            float* __restrict__ out, int n)
{
    __shared__ float buf[HD * TP];    // 17.4 KB, aliased Cs/As

    const int tid = threadIdx.x;
    const int node_base = blockIdx.x * 64;
    const int tn = tid & 31;          // node group: 2 lane-contiguous nodes
    const int tf = tid >> 5;          // feature group: 8 feats = 4 f32x2

    // stage counts -> buf[label][node] as floats
#pragma unroll
    for (int i = tid; i < 64 * 7; i += 256) {
        int nn = i & 63;
        int c  = i >> 6;              // word group 0..6 -> labels c*8 .. c*8+7
        int node = node_base + nn;
        uint4 w = make_uint4(0, 0, 0, 0);
        if (node < n)
            w = *reinterpret_cast<const uint4*>(lcnt + (size_t)node * CW + c * 4);
        u32 ws[4] = {w.x, w.y, w.z, w.w};
#pragma unroll
        for (int j = 0; j < 4; j++) {
            int l0 = c * 8 + j * 2;
            if (l0 < NL + 1)     buf[l0 * TP + nn]       = (float)(ws[j] & 0xFFFFu);
            if (l0 + 1 < NL + 1) buf[(l0 + 1) * TP + nn] = (float)(ws[j] >> 16);
        }
    }
    __syncthreads();

    ull acc[2][4];
    {   // init with b1
        ulonglong2 b01 = *reinterpret_cast<const ulonglong2*>(b1 + tf * 8);
        ulonglong2 b23 = *reinterpret_cast<const ulonglong2*>(b1 + tf * 8 + 4);
#pragma unroll
        for (int i = 0; i < 2; i++) {
            acc[i][0] = b01.x; acc[i][1] = b01.y;
            acc[i][2] = b23.x; acc[i][3] = b23.y;
        }
    }

    // phase 1: cnt' @ EW  (51 iterations)
#pragma unroll 3
    for (int l = 0; l < NL; l++) {
        float2 xv = *reinterpret_cast<const float2*>(buf + l * TP + tn * 2);
        const float* wrow = EW + l * HD + tf * 8;
        ulonglong2 w01 = *reinterpret_cast<const ulonglong2*>(wrow);
        ulonglong2 w23 = *reinterpret_cast<const ulonglong2*>(wrow + 4);
        ull xd[2] = {pack_dup(xv.x), pack_dup(xv.y)};
#pragma unroll
        for (int i = 0; i < 2; i++) {
            fma2(acc[i][0], xd[i], w01.x);
            fma2(acc[i][1], xd[i], w01.y);
            fma2(acc[i][2], xd[i], w23.x);
            fma2(acc[i][3], xd[i], w23.y);
        }
    }
    __syncthreads();                  // all count reads done before As overwrite

    // phase-1 epilogue: relu -> buf[feat][node] (As)
    {
        float vals[2][8];
#pragma unroll
        for (int i = 0; i < 2; i++) {
#pragma unroll
            for (int j2 = 0; j2 < 4; j2++) {
                float2 p = unpack2(acc[i][j2]);
                vals[i][j2 * 2 + 0] = fmaxf(p.x, 0.f);
                vals[i][j2 * 2 + 1] = fmaxf(p.y, 0.f);
            }
        }
#pragma unroll
        for (int j = 0; j < 8; j++) {
            float2 v = make_float2(vals[0][j], vals[1][j]);
            *reinterpret_cast<float2*>(buf + (tf * 8 + j) * TP + tn * 2) = v;
        }
    }
    __syncthreads();

    // phase 2: a @ W2  (64 iterations)
    {
        ulonglong2 b01 = *reinterpret_cast<const ulonglong2*>(b2 + tf * 8);
        ulonglong2 b23 = *reinterpret_cast<const ulonglong2*>(b2 + tf * 8 + 4);
#pragma unroll
        for (int i = 0; i < 2; i++) {
            acc[i][0] = b01.x; acc[i][1] = b01.y;
            acc[i][2] = b23.x; acc[i][3] = b23.y;
        }
    }

#pragma unroll 8
    for (int kk = 0; kk < HD; kk++) {
        float2 xv = *reinterpret_cast<const float2*>(buf + kk * TP + tn * 2);
        const float* wrow = W2 + kk * HD + tf * 8;
        ulonglong2 w01 = *reinterpret_cast<const ulonglong2*>(wrow);
        ulonglong2 w23 = *reinterpret_cast<const ulonglong2*>(wrow + 4);
        ull xd[2] = {pack_dup(xv.x), pack_dup(xv.y)};
#pragma unroll
        for (int i = 0; i < 2; i++) {
            fma2(acc[i][0], xd[i], w01.x);
            fma2(acc[i][1], xd[i], w01.y);
            fma2(acc[i][2], xd[i], w23.x);
            fma2(acc[i][3], xd[i], w23.y);
        }
    }

#pragma unroll
    for (int i = 0; i < 2; i++) {
        int node = node_base + tn * 2 + i;
        if (node >= n) continue;
        float2 p0 = unpack2(acc[i][0]);
        float2 p1 = unpack2(acc[i][1]);
        float2 p2 = unpack2(acc[i][2]);
        float2 p3 = unpack2(acc[i][3]);
        float* o = out + (size_t)node * HD + tf * 8;
        *reinterpret_cast<float4*>(o) =
            make_float4(fmaxf(p0.x, 0.f), fmaxf(p0.y, 0.f),
                        fmaxf(p1.x, 0.f), fmaxf(p1.y, 0.f));
        *reinterpret_cast<float4*>(o + 4) =
            make_float4(fmaxf(p2.x, 0.f), fmaxf(p2.y, 0.f),
                        fmaxf(p3.x, 0.f), fmaxf(p3.y, 0.f));
    }
}

// ---------------- warp-cooperative edge scatter (layer1, 64-dim) -------------
template <int DIM>
__global__ void __launch_bounds__(256)
scatter_kernel(const int* __restrict__ src,
               const int* __restrict__ dst,
               const float* __restrict__ h,
               float* __restrict__ agg, int E)
{
    const int LPE = DIM / 4;
    const int EPW = 32 / LPE;
    int warp = (blockIdx.x * blockDim.x + threadIdx.x) >> 5;
    int lane = threadIdx.x & 31;
    int base = warp * 32;
    if (base >= E) return;

    int s = 0, d = 0;
    if (base + lane < E) {
        s = __ldg(&src[base + lane]);
        d = __ldg(&dst[base + lane]);
    }

    const int sub = lane / LPE;
    const int j4  = lane % LPE;
    int m = E - base; if (m > 32) m = 32;

    if (m == 32) {
#pragma unroll
        for (int j = 0; j < 32; j += EPW) {
            int eidx = j + sub;
            int es = __shfl_sync(0xFFFFFFFFu, s, eidx);
            int ed = __shfl_sync(0xFFFFFFFFu, d, eidx);
            float4 v = *reinterpret_cast<const float4*>(h + (size_t)es * DIM + j4 * 4);
            atomicAdd(reinterpret_cast<float4*>(agg + (size_t)ed * DIM + j4 * 4), v);
        }
    } else {
        for (int j = 0; j < m; j += EPW) {
            int eidx = j + sub;
            int es = __shfl_sync(0xFFFFFFFFu, s, eidx & 31);
            int ed = __shfl_sync(0xFFFFFFFFu, d, eidx & 31);
            if (eidx < m) {
                float4 v = *reinterpret_cast<const float4*>(h + (size_t)es * DIM + j4 * 4);
                atomicAdd(reinterpret_cast<float4*>(agg + (size_t)ed * DIM + j4 * 4), v);
            }
        }
    }
}

// ---------------- fused 2-layer MLP (layer1) + mean-pool (64-node tile) ------
// Single aliased smem buffer buf[64][TP]: rows 0..15 stage X chunks (phase 1),
// whole buffer holds As for phase 2.
template <int K1>
__global__ void __launch_bounds__(256, 5)
mlp2_kernel(const float* __restrict__ x1, const float* __restrict__ x2,
            const float* __restrict__ W1, const float* __restrict__ b1,
            const float* __restrict__ W2, const float* __restrict__ b2,
            const int* __restrict__ gids,
            float* __restrict__ sums, float* __restrict__ cnts, int n)
{
    __shared__ float buf[HD * TP];    // 17.4 KB, aliased Xs/As

    const int tid = threadIdx.x;
    const int node_base = blockIdx.x * 64;
    const int tn = tid & 31;
    const int tf = tid >> 5;

    ull acc[2][4];
    {
        ulonglong2 b01 = *reinterpret_cast<const ulonglong2*>(b1 + tf * 8);
        ulonglong2 b23 = *reinterpret_cast<const ulonglong2*>(b1 + tf * 8 + 4);
#pragma unroll
        for (int i = 0; i < 2; i++) {
            acc[i][0] = b01.x; acc[i][1] = b01.y;
            acc[i][2] = b23.x; acc[i][3] = b23.y;
        }
    }

    for (int kc = 0; kc < K1; kc += 16) {
        if (kc > 0) __syncthreads();
        // stage Xs: 64 nodes x 4 float4 chunks = 256 loads, 1 per thread
        {
            int nn = tid & 63;
            int c  = tid >> 6;        // 0..3
            int node = node_base + nn;
            float4 v = make_float4(0.f, 0.f, 0.f, 0.f);
            if (node < n) {
                v = *reinterpret_cast<const float4*>(x1 + (size_t)node * K1 + kc + c * 4);
                float4 u = *reinterpret_cast<const float4*>(x2 + (size_t)node * K1 + kc + c * 4);
                v.x += u.x; v.y += u.y; v.z += u.z; v.w += u.w;
            }
            buf[(c * 4 + 0) * TP + nn] = v.x;
            buf[(c * 4 + 1) * TP + nn] = v.y;
            buf[(c * 4 + 2) * TP + nn] = v.z;
            buf[(c * 4 + 3) * TP + nn] = v.w;
        }
        __syncthreads();

#pragma unroll
        for (int kk = 0; kk < 16; kk++) {
            float2 xv = *reinterpret_cast<const float2*>(buf + kk * TP + tn * 2);
            const float* wrow = W1 + (kc + kk) * HD + tf * 8;
            ulonglong2 w01 = *reinterpret_cast<const ulonglong2*>(wrow);
            ulonglong2 w23 = *reinterpret_cast<const ulonglong2*>(wrow + 4);
            ull xd[2] = {pack_dup(xv.x), pack_dup(xv.y)};
#pragma unroll
            for (int i = 0; i < 2; i++) {
                fma2(acc[i][0], xd[i], w01.x);
                fma2(acc[i][1], xd[i], w01.y);
                fma2(acc[i][2], xd[i], w23.x);
                fma2(acc[i][3], xd[i], w23.y);
            }
        }
    }
    __syncthreads();                  // Xs reads done before As overwrite

    {
        float vals[2][8];
#pragma unroll
        for (int i = 0; i < 2; i++) {
#pragma unroll
            for (int j2 = 0; j2 < 4; j2++) {
                float2 p = unpack2(acc[i][j2]);
                vals[i][j2 * 2 + 0] = fmaxf(p.x, 0.f);
                vals[i][j2 * 2 + 1] = fmaxf(p.y, 0.f);
            }
        }
#pragma unroll
        for (int j = 0; j < 8; j++) {
            float2 v = make_float2(vals[0][j], vals[1][j]);
            *reinterpret_cast<float2*>(buf + (tf * 8 + j) * TP + tn * 2) = v;
        }
    }
    __syncthreads();

    {
        ulonglong2 b01 = *reinterpret_cast<const ulonglong2*>(b2 + tf * 8);
        ulonglong2 b23 = *reinterpret_cast<const ulonglong2*>(b2 + tf * 8 + 4);
#pragma unroll
        for (int i = 0; i < 2; i++) {
            acc[i][0] = b01.x; acc[i][1] = b01.y;
            acc[i][2] = b23.x; acc[i][3] = b23.y;
        }
    }

#pragma unroll 8
    for (int kk = 0; kk < HD; kk++) {
        float2 xv = *reinterpret_cast<const float2*>(buf + kk * TP + tn * 2);
        const float* wrow = W2 + kk * HD + tf * 8;
        ulonglong2 w01 = *reinterpret_cast<const ulonglong2*>(wrow);
        ulonglong2 w23 = *reinterpret_cast<const ulonglong2*>(wrow + 4);
        ull xd[2] = {pack_dup(xv.x), pack_dup(xv.y)};
#pragma unroll
        for (int i = 0; i < 2; i++) {
            fma2(acc[i][0], xd[i], w01.x);
            fma2(acc[i][1], xd[i], w01.y);
            fma2(acc[i][2], xd[i], w23.x);
            fma2(acc[i][3], xd[i], w23.y);
        }
    }

#pragma unroll
    for (int i = 0; i < 2; i++) {
        int node = node_base + tn * 2 + i;
        if (node >= n) continue;
        float2 p0 = unpack2(acc[i][0]);
        float2 p1 = unpack2(acc[i][1]);
        float2 p2 = unpack2(acc[i][2]);
        float2 p3 = unpack2(acc[i][3]);
        float4 ra = make_float4(fmaxf(p0.x, 0.f), fmaxf(p0.y, 0.f),
                                fmaxf(p1.x, 0.f), fmaxf(p1.y, 0.f));
        float4 rb = make_float4(fmaxf(p2.x, 0.f), fmaxf(p2.y, 0.f),
                                fmaxf(p3.x, 0.f), fmaxf(p3.y, 0.f));
        int g = gids[node];
        float* sg = sums + (size_t)g * HD + tf * 8;
        atomicAdd(reinterpret_cast<float4*>(sg),     ra);
        atomicAdd(reinterpret_cast<float4*>(sg + 4), rb);
        if (tf == 0) atomicAdd(&cnts[g], 1.0f);
    }
}

// ---------------- scorer: out[g] = relu(mean_h @ sw1 + sb1) @ sw2 + sb2 -----
__global__ void scorer_kernel(const float* __restrict__ sums,
                              const float* __restrict__ cnts,
                              const float* __restrict__ sw1,
                              const float* __restrict__ sb1,
                              const float* __restrict__ sw2,
                              const float* __restrict__ sb2,
                              float* __restrict__ out)
{
    int g = blockIdx.x;
    int f = threadIdx.x;           // 64 threads
    float cnt = fmaxf(cnts[g], 1.0f);
    float inv = 1.0f / cnt;
    float acc = sb1[f];
    const float* sg = sums + (size_t)g * HD;
    for (int k = 0; k < HD; k++) acc += (sg[k] * inv) * sw1[k * HD + f];
    float hf = fmaxf(acc, 0.f) * sw2[f];

    __shared__ float red[HD];
    red[f] = hf;
    __syncthreads();
    if (f < 32) red[f] += red[f + 32];
    __syncthreads();
    if (f < 32) {
        float v = red[f];
#pragma unroll
        for (int off = 16; off > 0; off >>= 1)
            v += __shfl_down_sync(0xFFFFFFFFu, v, off);
        if (f == 0) out[g] = v + sb2[0];
    }
}

// ---------------- launcher --------------------------------------------------
extern "C" void kernel_launch(void* const* d_in, const int* in_sizes, int n_in,
                              void* d_out, int out_size)
{
    const int*   labels = (const int*)  d_in[0];
    const int*   src    = (const int*)  d_in[1];
    const int*   dst    = (const int*)  d_in[2];
    const int*   gids   = (const int*)  d_in[3];
    const float* emb    = (const float*)d_in[4];
    const float* w1_0   = (const float*)d_in[5];
    const float* b1_0   = (const float*)d_in[6];
    const float* w2_0   = (const float*)d_in[7];
    const float* b2_0   = (const float*)d_in[8];
    const float* w1_1   = (const float*)d_in[9];
    const float* b1_1   = (const float*)d_in[10];
    const float* w2_1   = (const float*)d_in[11];
    const float* b2_1   = (const float*)d_in[12];
    const float* sw1    = (const float*)d_in[13];
    const float* sb1    = (const float*)d_in[14];
    const float* sw2    = (const float*)d_in[15];
    const float* sb2    = (const float*)d_in[16];
    float* out = (float*)d_out;

    int N = in_sizes[0];
    int E = in_sizes[1];
    int G = out_size;

    if (N > NMAX) N = NMAX;
    if (E > EMAX) E = EMAX;
    if (G > GMAX) G = GMAX;

    u32 *lcnt;
    float *EW, *h1, *ag1, *sums, *cnts;
    cudaGetSymbolAddress((void**)&lcnt, g_lcnt);
    cudaGetSymbolAddress((void**)&EW,   g_EW);
    cudaGetSymbolAddress((void**)&h1,   g_h1);
    cudaGetSymbolAddress((void**)&ag1,  g_ag1);
    cudaGetSymbolAddress((void**)&sums, g_sum);
    cudaGetSymbolAddress((void**)&cnts, g_cnt);

    const int TB = 256;
    const int NB = (N + 63) / 64;                   // MLP node tiles (64/block)
    const int SB = ((E + 31) / 32 + 7) / 8;         // scatter blocks (8 warps)

    // 1. zero accumulators + seed self-label counts; EW = emb @ W1_0
    init_kernel<<<(N * HD + TB - 1) / TB, TB>>>(labels, N, G, lcnt, ag1, sums, cnts);
    ew_kernel<<<(NL * HD + TB - 1) / TB, TB>>>(emb, w1_0, EW);
    // 2. layer0: label-histogram scatter (1 x 4B atomic per edge)
    label_scatter_kernel<<<(E + TB - 1) / TB, TB>>>(src, dst, labels, lcnt, E);
    // 3. layer0 fused MLP from counts: h1 = relu(relu(cnt'@EW + b1)@W2 + b2)
    mlp0_kernel<<<NB, 256>>>(lcnt, EW, b1_0, w2_0, b2_0, h1, N);
    // 4. layer1 scatter: ag1[dst] += h1[src]  (64-dim, warp-cooperative)
    scatter_kernel<HD><<<SB, TB>>>(src, dst, h1, ag1, E);
    // 5. layer1 fused MLP + mean-pool accumulation
    mlp2_kernel<HD><<<NB, 256>>>(h1, ag1, w1_1, b1_1, w2_1, b2_1,
                                 gids, sums, cnts, N);
    // 6. scorer
    scorer_kernel<<<G, HD>>>(sums, cnts, sw1, sb1, sw2, sb2, out);
}

// round 15
// speedup vs baseline: 1.1593x; 1.1593x over previous
#include <cuda_runtime.h>
#include <cuda_bf16.h>

typedef unsigned long long ull;
typedef unsigned int u32;

// ---------------- problem constants (fixed shapes per reference) -------------
#define NMAX   50000
#define EMAX   1250000
#define GMAX   1024
#define LD     32      // label/embedding dim
#define HD     64      // hidden dim
#define NL     51      // number of labels (MAX_LABEL+1)
#define CW     32      // packed u16 count words per node (64 halves >= NL)
#define XP     132     // smem row pitch (floats)

// ---------------- device scratch (no allocation allowed) --------------------
__device__ u32   g_lcnt[NMAX * CW];  // per-node packed u16 label histograms
__device__ ull   g_ewd [NL * HD];    // dup'd (emb @ W1_0):  (w,w) per entry
__device__ ull   g_w2d0[HD * HD];    // dup'd w2_0
__device__ ull   g_w1d1[HD * HD];    // dup'd w1_1
__device__ ull   g_w2d1[HD * HD];    // dup'd w2_1
__device__ float g_h1 [NMAX * HD];   // layer0 output h
__device__ float g_ag1[NMAX * HD];   // layer1 aggregation
__device__ float g_sum[GMAX * HD];   // per-graph feature sums
__device__ float g_cnt[GMAX];        // per-graph node counts

// ---------------- packed f32x2 helpers (Blackwell FFMA2) --------------------
__device__ __forceinline__ void fma2(ull& acc, ull a, ull b) {
    asm("fma.rn.f32x2 %0, %1, %2, %0;" : "+l"(acc) : "l"(a), "l"(b));
}
__device__ __forceinline__ ull pack_dup(float x) {
    ull r;
    asm("mov.b64 %0, {%1, %1};" : "=l"(r) : "r"(__float_as_uint(x)));
    return r;
}
__device__ __forceinline__ float2 unpack2(ull v) {
    unsigned lo, hi;
    asm("mov.b64 {%0, %1}, %2;" : "=r"(lo), "=r"(hi) : "l"(v));
    return make_float2(__uint_as_float(lo), __uint_as_float(hi));
}

// ---------------- init: zero accumulators, seed self-label counts ------------
__global__ void init_kernel(const int* __restrict__ labels, int n, int g,
                            u32* __restrict__ lcnt,
                            float* __restrict__ ag1,
                            float* __restrict__ sums, float* __restrict__ cnts)
{
    int idx = blockIdx.x * blockDim.x + threadIdx.x;
    if (idx < n) {
        uint4 z = make_uint4(0, 0, 0, 0);
        uint4* p = reinterpret_cast<uint4*>(lcnt + (size_t)idx * CW);
#pragma unroll
        for (int w = 0; w < CW / 4; w++) p[w] = z;
        int lab = labels[idx];
        lab = lab < 0 ? 0 : (lab > NL - 1 ? NL - 1 : lab);
        lcnt[(size_t)idx * CW + (lab >> 1)] = 1u << ((lab & 1) * 16);
    }
    if (idx < n * HD) ag1[idx] = 0.f;
    if (idx < g * HD) sums[idx] = 0.f;
    if (idx < g)      cnts[idx] = 0.f;
}

// ---------------- EWd = dup(emb @ W1_0)  (51 x 64, tiny) ---------------------
__global__ void ew_kernel(const float* __restrict__ emb,
                          const float* __restrict__ W1,
                          ull* __restrict__ EWd)
{
    int idx = blockIdx.x * blockDim.x + threadIdx.x;
    if (idx >= NL * HD) return;
    int l = idx / HD, f = idx % HD;
    float s = 0.f;
#pragma unroll
    for (int k = 0; k < LD; k++) s += emb[l * LD + k] * W1[k * HD + f];
    EWd[idx] = pack_dup(s);
}

// ---------------- duplicate the three 64x64 weight matrices ------------------
__global__ void dup_kernel(const float* __restrict__ w2_0,
                           const float* __restrict__ w1_1,
                           const float* __restrict__ w2_1,
                           ull* __restrict__ d2_0, ull* __restrict__ d1_1,
                           ull* __restrict__ d2_1)
{
    int idx = blockIdx.x * blockDim.x + threadIdx.x;
    if (idx >= HD * HD) return;
    d2_0[idx] = pack_dup(w2_0[idx]);
    d1_1[idx] = pack_dup(w1_1[idx]);
    d2_1[idx] = pack_dup(w2_1[idx]);
}

// ---------------- layer0 edge pass: label histogram scatter ------------------
__global__ void __launch_bounds__(256)
label_scatter_kernel(const int* __restrict__ src, const int* __restrict__ dst,
                     const int* __restrict__ labels, u32* __restrict__ lcnt, int E)
{
    int e = blockIdx.x * blockDim.x + threadIdx.x;
    if (e >= E) return;
    int s = __ldg(&src[e]);
    int d = __ldg(&dst[e]);
    int lab = __ldg(&labels[s]);
    lab = lab < 0 ? 0 : (lab > NL - 1 ? NL - 1 : lab);
    atomicAdd(&lcnt[(size_t)d * CW + (lab >> 1)], 1u << ((lab & 1) * 16));
}

// ---------------- layer0 fused MLP from label counts (128-node tile) ---------
// phase 1: a = relu(b1 + cnt' @ EW)   phase 2: h1 = relu(a @ W2 + b2)
// 256 threads; thread = 4 nodes x 8 feats, node-pair packed FFMA2 accumulators.
// X operand read directly as ulonglong2 from smem (no dup MOVs); weights are
// pre-duplicated (w,w) 64-bit words in global (uniform LDG.128, L1-hot).
__global__ void __launch_bounds__(256, 4)
mlp0_kernel(const u32* __restrict__ lcnt,
            const ull* __restrict__ EWd, const float* __restrict__ b1,
            const ull* __restrict__ W2d, const float* __restrict__ b2,
            float* __restrict__ out, int n)
{
    __shared__ __align__(16) float buf[HD * XP];   // 33.8 KB, aliased Cs/As

    const int tid = threadIdx.x;
    const int node_base = blockIdx.x * 128;
    const int tn = tid & 31;          // node group: 4 lane-contiguous nodes
    const int tf = tid >> 5;          // feature group: 8 feats

    // stage counts -> buf[label][node] as floats
#pragma unroll
    for (int i = tid; i < 128 * 7; i += 256) {
        int nn = i & 127;
        int c  = i >> 7;              // word group 0..6 -> labels c*8 .. c*8+7
        int node = node_base + nn;
        uint4 w = make_uint4(0, 0, 0, 0);
        if (node < n)
            w = *reinterpret_cast<const uint4*>(lcnt + (size_t)node * CW + c * 4);
        u32 ws[4] = {w.x, w.y, w.z, w.w};
#pragma unroll
        for (int j = 0; j < 4; j++) {
            int l0 = c * 8 + j * 2;
            if (l0 < NL + 1)     buf[l0 * XP + nn]       = (float)(ws[j] & 0xFFFFu);
            if (l0 + 1 < NL + 1) buf[(l0 + 1) * XP + nn] = (float)(ws[j] >> 16);
        }
    }
    __syncthreads();

    // acc[p][f]: p=0 -> nodes (4tn,4tn+1), p=1 -> (4tn+2,4tn+3); feature tf*8+f
    ull acc[2][8];
#pragma unroll
    for (int f = 0; f < 8; f++) {
        ull b = pack_dup(b1[tf * 8 + f]);
        acc[0][f] = b; acc[1][f] = b;
    }

    // phase 1: cnt' @ EW  (51 iterations)
#pragma unroll 3
    for (int l = 0; l < NL; l++) {
        ulonglong2 xp = *reinterpret_cast<const ulonglong2*>(buf + l * XP + tn * 4);
        const ull* wd = EWd + l * HD + tf * 8;
        ulonglong2 w0 = *reinterpret_cast<const ulonglong2*>(wd);
        ulonglong2 w1 = *reinterpret_cast<const ulonglong2*>(wd + 2);
        ulonglong2 w2 = *reinterpret_cast<const ulonglong2*>(wd + 4);
        ulonglong2 w3 = *reinterpret_cast<const ulonglong2*>(wd + 6);
        fma2(acc[0][0], xp.x, w0.x); fma2(acc[1][0], xp.y, w0.x);
        fma2(acc[0][1], xp.x, w0.y); fma2(acc[1][1], xp.y, w0.y);
        fma2(acc[0][2], xp.x, w1.x); fma2(acc[1][2], xp.y, w1.x);
        fma2(acc[0][3], xp.x, w1.y); fma2(acc[1][3], xp.y, w1.y);
        fma2(acc[0][4], xp.x, w2.x); fma2(acc[1][4], xp.y, w2.x);
        fma2(acc[0][5], xp.x, w2.y); fma2(acc[1][5], xp.y, w2.y);
        fma2(acc[0][6], xp.x, w3.x); fma2(acc[1][6], xp.y, w3.x);
        fma2(acc[0][7], xp.x, w3.y); fma2(acc[1][7], xp.y, w3.y);
    }
    __syncthreads();                  // all count reads done before As overwrite

    // phase-1 epilogue: relu -> buf[feat][node] (As)
#pragma unroll
    for (int f = 0; f < 8; f++) {
        float2 a = unpack2(acc[0][f]);
        float2 b = unpack2(acc[1][f]);
        float4 v = make_float4(fmaxf(a.x, 0.f), fmaxf(a.y, 0.f),
                               fmaxf(b.x, 0.f), fmaxf(b.y, 0.f));
        *reinterpret_cast<float4*>(buf + (tf * 8 + f) * XP + tn * 4) = v;
    }
    __syncthreads();

    // phase 2: a @ W2  (64 iterations)
#pragma unroll
    for (int f = 0; f < 8; f++) {
        ull b = pack_dup(b2[tf * 8 + f]);
        acc[0][f] = b; acc[1][f] = b;
    }

#pragma unroll 8
    for (int kk = 0; kk < HD; kk++) {
        ulonglong2 xp = *reinterpret_cast<const ulonglong2*>(buf + kk * XP + tn * 4);
        const ull* wd = W2d + kk * HD + tf * 8;
        ulonglong2 w0 = *reinterpret_cast<const ulonglong2*>(wd);
        ulonglong2 w1 = *reinterpret_cast<const ulonglong2*>(wd + 2);
        ulonglong2 w2 = *reinterpret_cast<const ulonglong2*>(wd + 4);
        ulonglong2 w3 = *reinterpret_cast<const ulonglong2*>(wd + 6);
        fma2(acc[0][0], xp.x, w0.x); fma2(acc[1][0], xp.y, w0.x);
        fma2(acc[0][1], xp.x, w0.y); fma2(acc[1][1], xp.y, w0.y);
        fma2(acc[0][2], xp.x, w1.x); fma2(acc[1][2], xp.y, w1.x);
        fma2(acc[0][3], xp.x, w1.y); fma2(acc[1][3], xp.y, w1.y);
        fma2(acc[0][4], xp.x, w2.x); fma2(acc[1][4], xp.y, w2.x);
        fma2(acc[0][5], xp.x, w2.y); fma2(acc[1][5], xp.y, w2.y);
        fma2(acc[0][6], xp.x, w3.x); fma2(acc[1][6], xp.y, w3.x);
        fma2(acc[0][7], xp.x, w3.y); fma2(acc[1][7], xp.y, w3.y);
    }

    // phase-2 epilogue: per-node float4 writes
#pragma unroll
    for (int p = 0; p < 2; p++) {
        float2 v[8];
#pragma unroll
        for (int f = 0; f < 8; f++) v[f] = unpack2(acc[p][f]);
        int n0 = node_base + tn * 4 + p * 2;
#pragma unroll
        for (int i = 0; i < 2; i++) {
            int node = n0 + i;
            if (node >= n) continue;
            float* o = out + (size_t)node * HD + tf * 8;
            float x0 = i ? v[0].y : v[0].x, x1 = i ? v[1].y : v[1].x;
            float x2 = i ? v[2].y : v[2].x, x3 = i ? v[3].y : v[3].x;
            float x4 = i ? v[4].y : v[4].x, x5 = i ? v[5].y : v[5].x;
            float x6 = i ? v[6].y : v[6].x, x7 = i ? v[7].y : v[7].x;
            *reinterpret_cast<float4*>(o) =
                make_float4(fmaxf(x0, 0.f), fmaxf(x1, 0.f), fmaxf(x2, 0.f), fmaxf(x3, 0.f));
            *reinterpret_cast<float4*>(o + 4) =
                make_float4(fmaxf(x4, 0.f), fmaxf(x5, 0.f), fmaxf(x6, 0.f), fmaxf(x7, 0.f));
        }
    }
}

// ---------------- warp-cooperative edge scatter (layer1, 64-dim) -------------
template <int DIM>
__global__ void __launch_bounds__(256)
scatter_kernel(const int* __restrict__ src,
               const int* __restrict__ dst,
               const float* __restrict__ h,
               float* __restrict__ agg, int E)
{
    const int LPE = DIM / 4;
    const int EPW = 32 / LPE;
    int warp = (blockIdx.x * blockDim.x + threadIdx.x) >> 5;
    int lane = threadIdx.x & 31;
    int base = warp * 32;
    if (base >= E) return;

    int s = 0, d = 0;
    if (base + lane < E) {
        s = __ldg(&src[base + lane]);
        d = __ldg(&dst[base + lane]);
    }

    const int sub = lane / LPE;
    const int j4  = lane % LPE;
    int m = E - base; if (m > 32) m = 32;

    if (m == 32) {
#pragma unroll
        for (int j = 0; j < 32; j += EPW) {
            int eidx = j + sub;
            int es = __shfl_sync(0xFFFFFFFFu, s, eidx);
            int ed = __shfl_sync(0xFFFFFFFFu, d, eidx);
            float4 v = *reinterpret_cast<const float4*>(h + (size_t)es * DIM + j4 * 4);
            atomicAdd(reinterpret_cast<float4*>(agg + (size_t)ed * DIM + j4 * 4), v);
        }
    } else {
        for (int j = 0; j < m; j += EPW) {
            int eidx = j + sub;
            int es = __shfl_sync(0xFFFFFFFFu, s, eidx & 31);
            int ed = __shfl_sync(0xFFFFFFFFu, d, eidx & 31);
            if (eidx < m) {
                float4 v = *reinterpret_cast<const float4*>(h + (size_t)es * DIM + j4 * 4);
                atomicAdd(reinterpret_cast<float4*>(agg + (size_t)ed * DIM + j4 * 4), v);
            }
        }
    }
}

// ---------------- fused 2-layer MLP (layer1) + mean-pool (128-node tile) -----
// Node-pair packed accumulators; pre-duplicated weights.
__global__ void __launch_bounds__(256, 4)
mlp2_kernel(const float* __restrict__ x1, const float* __restrict__ x2,
            const ull* __restrict__ W1d, const float* __restrict__ b1,
            const ull* __restrict__ W2d, const float* __restrict__ b2,
            const int* __restrict__ gids,
            float* __restrict__ sums, float* __restrict__ cnts, int n)
{
    __shared__ __align__(16) float buf[HD * XP];   // 33.8 KB, aliased Xs/As

    const int tid = threadIdx.x;
    const int node_base = blockIdx.x * 128;
    const int tn = tid & 31;
    const int tf = tid >> 5;

    ull acc[2][8];
#pragma unroll
    for (int f = 0; f < 8; f++) {
        ull b = pack_dup(b1[tf * 8 + f]);
        acc[0][f] = b; acc[1][f] = b;
    }

    for (int kc = 0; kc < HD; kc += 16) {
        if (kc > 0) __syncthreads();
#pragma unroll
        for (int i = tid; i < 128 * 4; i += 256) {
            int nn = i & 127;
            int c  = i >> 7;
            int node = node_base + nn;
            float4 v = make_float4(0.f, 0.f, 0.f, 0.f);
            if (node < n) {
                v = *reinterpret_cast<const float4*>(x1 + (size_t)node * HD + kc + c * 4);
                float4 u = *reinterpret_cast<const float4*>(x2 + (size_t)node * HD + kc + c * 4);
                v.x += u.x; v.y += u.y; v.z += u.z; v.w += u.w;
            }
            buf[(c * 4 + 0) * XP + nn] = v.x;
            buf[(c * 4 + 1) * XP + nn] = v.y;
            buf[(c * 4 + 2) * XP + nn] = v.z;
            buf[(c * 4 + 3) * XP + nn] = v.w;
        }
        __syncthreads();

#pragma unroll
        for (int kk = 0; kk < 16; kk++) {
            ulonglong2 xp = *reinterpret_cast<const ulonglong2*>(buf + kk * XP + tn * 4);
            const ull* wd = W1d + (kc + kk) * HD + tf * 8;
            ulonglong2 w0 = *reinterpret_cast<const ulonglong2*>(wd);
            ulonglong2 w1 = *reinterpret_cast<const ulonglong2*>(wd + 2);
            ulonglong2 w2 = *reinterpret_cast<const ulonglong2*>(wd + 4);
            ulonglong2 w3 = *reinterpret_cast<const ulonglong2*>(wd + 6);
            fma2(acc[0][0], xp.x, w0.x); fma2(acc[1][0], xp.y, w0.x);
            fma2(acc[0][1], xp.x, w0.y); fma2(acc[1][1], xp.y, w0.y);
            fma2(acc[0][2], xp.x, w1.x); fma2(acc[1][2], xp.y, w1.x);
            fma2(acc[0][3], xp.x, w1.y); fma2(acc[1][3], xp.y, w1.y);
            fma2(acc[0][4], xp.x, w2.x); fma2(acc[1][4], xp.y, w2.x);
            fma2(acc[0][5], xp.x, w2.y); fma2(acc[1][5], xp.y, w2.y);
            fma2(acc[0][6], xp.x, w3.x); fma2(acc[1][6], xp.y, w3.x);
            fma2(acc[0][7], xp.x, w3.y); fma2(acc[1][7], xp.y, w3.y);
        }
    }
    __syncthreads();                  // Xs reads done before As overwrite

    // phase-1 epilogue: relu -> buf[feat][node]
#pragma unroll
    for (int f = 0; f < 8; f++) {
        float2 a = unpack2(acc[0][f]);
        float2 b = unpack2(acc[1][f]);
        float4 v = make_float4(fmaxf(a.x, 0.f), fmaxf(a.y, 0.f),
                               fmaxf(b.x, 0.f), fmaxf(b.y, 0.f));
        *reinterpret_cast<float4*>(buf + (tf * 8 + f) * XP + tn * 4) = v;
    }
    __syncthreads();

    // phase 2
#pragma unroll
    for (int f = 0; f < 8; f++) {
        ull b = pack_dup(b2[tf * 8 + f]);
        acc[0][f] = b; acc[1][f] = b;
    }

#pragma unroll 8
    for (int kk = 0; kk < HD; kk++) {
        ulonglong2 xp = *reinterpret_cast<const ulonglong2*>(buf + kk * XP + tn * 4);
        const ull* wd = W2d + kk * HD + tf * 8;
        ulonglong2 w0 = *reinterpret_cast<const ulonglong2*>(wd);
        ulonglong2 w1 = *reinterpret_cast<const ulonglong2*>(wd + 2);
        ulonglong2 w2 = *reinterpret_cast<const ulonglong2*>(wd + 4);
        ulonglong2 w3 = *reinterpret_cast<const ulonglong2*>(wd + 6);
        fma2(acc[0][0], xp.x, w0.x); fma2(acc[1][0], xp.y, w0.x);
        fma2(acc[0][1], xp.x, w0.y); fma2(acc[1][1], xp.y, w0.y);
        fma2(acc[0][2], xp.x, w1.x); fma2(acc[1][2], xp.y, w1.x);
        fma2(acc[0][3], xp.x, w1.y); fma2(acc[1][3], xp.y, w1.y);
        fma2(acc[0][4], xp.x, w2.x); fma2(acc[1][4], xp.y, w2.x);
        fma2(acc[0][5], xp.x, w2.y); fma2(acc[1][5], xp.y, w2.y);
        fma2(acc[0][6], xp.x, w3.x); fma2(acc[1][6], xp.y, w3.x);
        fma2(acc[0][7], xp.x, w3.y); fma2(acc[1][7], xp.y, w3.y);
    }

    // phase-2 epilogue: relu + pooled atomics
#pragma unroll
    for (int p = 0; p < 2; p++) {
        float2 v[8];
#pragma unroll
        for (int f = 0; f < 8; f++) v[f] = unpack2(acc[p][f]);
        int n0 = node_base + tn * 4 + p * 2;
#pragma unroll
        for (int i = 0; i < 2; i++) {
            int node = n0 + i;
            if (node >= n) continue;
            float x0 = i ? v[0].y : v[0].x, x1 = i ? v[1].y : v[1].x;
            float x2 = i ? v[2].y : v[2].x, x3 = i ? v[3].y : v[3].x;
            float x4 = i ? v[4].y : v[4].x, x5 = i ? v[5].y : v[5].x;
            float x6 = i ? v[6].y : v[6].x, x7 = i ? v[7].y : v[7].x;
            float4 ra = make_float4(fmaxf(x0, 0.f), fmaxf(x1, 0.f),
                                    fmaxf(x2, 0.f), fmaxf(x3, 0.f));
            float4 rb = make_float4(fmaxf(x4, 0.f), fmaxf(x5, 0.f),
                                    fmaxf(x6, 0.f), fmaxf(x7, 0.f));
            int g = gids[node];
            float* sg = sums + (size_t)g * HD + tf * 8;
            atomicAdd(reinterpret_cast<float4*>(sg),     ra);
            atomicAdd(reinterpret_cast<float4*>(sg + 4), rb);
            if (tf == 0) atomicAdd(&cnts[g], 1.0f);
        }
    }
}

// ---------------- scorer: out[g] = relu(mean_h @ sw1 + sb1) @ sw2 + sb2 -----
__global__ void scorer_kernel(const float* __restrict__ sums,
                              const float* __restrict__ cnts,
                              const float* __restrict__ sw1,
                              const float* __restrict__ sb1,
                              const float* __restrict__ sw2,
                              const float* __restrict__ sb2,
                              float* __restrict__ out)
{
    int g = blockIdx.x;
    int f = threadIdx.x;           // 64 threads
    float cnt = fmaxf(cnts[g], 1.0f);
    float inv = 1.0f / cnt;
    float acc = sb1[f];
    const float* sg = sums + (size_t)g * HD;
    for (int k = 0; k < HD; k++) acc += (sg[k] * inv) * sw1[k * HD + f];
    float hf = fmaxf(acc, 0.f) * sw2[f];

    __shared__ float red[HD];
    red[f] = hf;
    __syncthreads();
    if (f < 32) red[f] += red[f + 32];
    __syncthreads();
    if (f < 32) {
        float v = red[f];
#pragma unroll
        for (int off = 16; off > 0; off >>= 1)
            v += __shfl_down_sync(0xFFFFFFFFu, v, off);
        if (f == 0) out[g] = v + sb2[0];
    }
}

// ---------------- launcher --------------------------------------------------
extern "C" void kernel_launch(void* const* d_in, const int* in_sizes, int n_in,
                              void* d_out, int out_size)
{
    const int*   labels = (const int*)  d_in[0];
    const int*   src    = (const int*)  d_in[1];
    const int*   dst    = (const int*)  d_in[2];
    const int*   gids   = (const int*)  d_in[3];
    const float* emb    = (const float*)d_in[4];
    const float* w1_0   = (const float*)d_in[5];
    const float* b1_0   = (const float*)d_in[6];
    const float* w2_0   = (const float*)d_in[7];
    const float* b2_0   = (const float*)d_in[8];
    const float* w1_1   = (const float*)d_in[9];
    const float* b1_1   = (const float*)d_in[10];
    const float* w2_1   = (const float*)d_in[11];
    const float* b2_1   = (const float*)d_in[12];
    const float* sw1    = (const float*)d_in[13];
    const float* sb1    = (const float*)d_in[14];
    const float* sw2    = (const float*)d_in[15];
    const float* sb2    = (const float*)d_in[16];
    float* out = (float*)d_out;

    int N = in_sizes[0];
    int E = in_sizes[1];
    int G = out_size;

    if (N > NMAX) N = NMAX;
    if (E > EMAX) E = EMAX;
    if (G > GMAX) G = GMAX;

    u32 *lcnt;
    ull *ewd, *w2d0, *w1d1, *w2d1;
    float *h1, *ag1, *sums, *cnts;
    cudaGetSymbolAddress((void**)&lcnt, g_lcnt);
    cudaGetSymbolAddress((void**)&ewd,  g_ewd);
    cudaGetSymbolAddress((void**)&w2d0, g_w2d0);
    cudaGetSymbolAddress((void**)&w1d1, g_w1d1);
    cudaGetSymbolAddress((void**)&w2d1, g_w2d1);
    cudaGetSymbolAddress((void**)&h1,   g_h1);
    cudaGetSymbolAddress((void**)&ag1,  g_ag1);
    cudaGetSymbolAddress((void**)&sums, g_sum);
    cudaGetSymbolAddress((void**)&cnts, g_cnt);

    const int TB = 256;
    const int NB = (N + 127) / 128;                 // MLP node tiles
    const int SB = ((E + 31) / 32 + 7) / 8;         // scatter blocks (8 warps)

    // 1. zero accumulators + seed self-label counts; weight prep
    init_kernel<<<(N * HD + TB - 1) / TB, TB>>>(labels, N, G, lcnt, ag1, sums, cnts);
    ew_kernel<<<(NL * HD + TB - 1) / TB, TB>>>(emb, w1_0, ewd);
    dup_kernel<<<(HD * HD + TB - 1) / TB, TB>>>(w2_0, w1_1, w2_1, w2d0, w1d1, w2d1);
    // 2. layer0: label-histogram scatter (1 x 4B atomic per edge)
    label_scatter_kernel<<<(E + TB - 1) / TB, TB>>>(src, dst, labels, lcnt, E);
    // 3. layer0 fused MLP from counts: h1 = relu(relu(cnt'@EW + b1)@W2 + b2)
    mlp0_kernel<<<NB, 256>>>(lcnt, ewd, b1_0, w2d0, b2_0, h1, N);
    // 4. layer1 scatter: ag1[dst] += h1[src]  (64-dim, warp-cooperative)
    scatter_kernel<HD><<<SB, TB>>>(src, dst, h1, ag1, E);
    // 5. layer1 fused MLP + mean-pool accumulation
    mlp2_kernel<<<NB, 256>>>(h1, ag1, w1d1, b1_1, w2d1, b2_1,
                             gids, sums, cnts, N);
    // 6. scorer
    scorer_kernel<<<G, HD>>>(sums, cnts, sw1, sb1, sw2, sb2, out);
}

// round 16
// speedup vs baseline: 1.3403x; 1.1561x over previous
#include <cuda_runtime.h>
#include <cuda_bf16.h>

typedef unsigned long long ull;
typedef unsigned int u32;

// ---------------- problem constants (fixed shapes per reference) -------------
#define NMAX   50000
#define EMAX   1250000
#define GMAX   1024
#define LD     32      // label/embedding dim
#define HD     64      // hidden dim
#define NL     51      // number of labels (MAX_LABEL+1)
#define CW     32      // packed u16 count words per node (64 halves >= NL)
#define XP     132     // smem row pitch (floats)

// ---------------- device scratch (no allocation allowed) --------------------
__device__ u32   g_lcnt[NMAX * CW];  // per-node packed u16 label histograms
__device__ float g_EW  [NL * HD];    // emb @ W1_0  (51 x 64)
__device__ float g_h1 [NMAX * HD];   // layer0 output h
__device__ float g_ag1[NMAX * HD];   // layer1 aggregation
__device__ float g_sum[GMAX * HD];   // per-graph feature sums
__device__ float g_cnt[GMAX];        // per-graph node counts

// ---------------- packed f32x2 helpers (Blackwell FFMA2) --------------------
__device__ __forceinline__ void fma2(ull& acc, ull a, ull b) {
    asm("fma.rn.f32x2 %0, %1, %2, %0;" : "+l"(acc) : "l"(a), "l"(b));
}
__device__ __forceinline__ ull pack_dup(float x) {
    ull r;
    asm("mov.b64 %0, {%1, %1};" : "=l"(r) : "r"(__float_as_uint(x)));
    return r;
}
__device__ __forceinline__ float2 unpack2(ull v) {
    unsigned lo, hi;
    asm("mov.b64 {%0, %1}, %2;" : "=r"(lo), "=r"(hi) : "l"(v));
    return make_float2(__uint_as_float(lo), __uint_as_float(hi));
}

// ---------------- init: zero accumulators, seed self-label counts ------------
__global__ void init_kernel(const int* __restrict__ labels, int n, int g,
                            u32* __restrict__ lcnt,
                            float* __restrict__ ag1,
                            float* __restrict__ sums, float* __restrict__ cnts)
{
    int idx = blockIdx.x * blockDim.x + threadIdx.x;
    if (idx < n) {
        uint4 z = make_uint4(0, 0, 0, 0);
        uint4* p = reinterpret_cast<uint4*>(lcnt + (size_t)idx * CW);
#pragma unroll
        for (int w = 0; w < CW / 4; w++) p[w] = z;
        int lab = labels[idx];
        lab = lab < 0 ? 0 : (lab > NL - 1 ? NL - 1 : lab);
        lcnt[(size_t)idx * CW + (lab >> 1)] = 1u << ((lab & 1) * 16);
    }
    if (idx < n * HD) ag1[idx] = 0.f;
    if (idx < g * HD) sums[idx] = 0.f;
    if (idx < g)      cnts[idx] = 0.f;
}

// ---------------- EW = emb @ W1_0  (51 x 64, tiny) ---------------------------
__global__ void ew_kernel(const float* __restrict__ emb,
                          const float* __restrict__ W1,
                          float* __restrict__ EW)
{
    int idx = blockIdx.x * blockDim.x + threadIdx.x;
    if (idx >= NL * HD) return;
    int l = idx / HD, f = idx % HD;
    float s = 0.f;
#pragma unroll
    for (int k = 0; k < LD; k++) s += emb[l * LD + k] * W1[k * HD + f];
    EW[idx] = s;
}

// ---------------- layer0 edge pass: label histogram scatter ------------------
__global__ void __launch_bounds__(256)
label_scatter_kernel(const int* __restrict__ src, const int* __restrict__ dst,
                     const int* __restrict__ labels, u32* __restrict__ lcnt, int E)
{
    int e = blockIdx.x * blockDim.x + threadIdx.x;
    if (e >= E) return;
    int s = __ldg(&src[e]);
    int d = __ldg(&dst[e]);
    int lab = __ldg(&labels[s]);
    lab = lab < 0 ? 0 : (lab > NL - 1 ? NL - 1 : lab);
    atomicAdd(&lcnt[(size_t)d * CW + (lab >> 1)], 1u << ((lab & 1) * 16));
}

// ---------------- layer0 fused MLP from label counts (128-node tile) ---------
// phase 1: a = relu(b1 + cnt' @ EW)   phase 2: h1 = relu(a @ W2 + b2)
// 256 threads; thread = 4 nodes x 8 feats (feature-pair FFMA2 accumulators).
// Hot loops software-pipelined: prefetch iter l+1's X/W while computing iter l.
__global__ void __launch_bounds__(256, 3)
mlp0_kernel(const u32* __restrict__ lcnt,
            const float* __restrict__ EW, const float* __restrict__ b1,
            const float* __restrict__ W2, const float* __restrict__ b2,
            float* __restrict__ out, int n)
{
    __shared__ __align__(16) float buf[HD * XP];   // 33.8 KB, aliased Cs/As

    const int tid = threadIdx.x;
    const int node_base = blockIdx.x * 128;
    const int tn = tid & 31;          // node group: 4 lane-contiguous nodes
    const int tf = tid >> 5;          // feature group: 8 feats = 4 f32x2

    // stage counts -> buf[label][node] as floats
#pragma unroll
    for (int i = tid; i < 128 * 7; i += 256) {
        int nn = i & 127;
        int c  = i >> 7;              // word group 0..6 -> labels c*8 .. c*8+7
        int node = node_base + nn;
        uint4 w = make_uint4(0, 0, 0, 0);
        if (node < n)
            w = *reinterpret_cast<const uint4*>(lcnt + (size_t)node * CW + c * 4);
        u32 ws[4] = {w.x, w.y, w.z, w.w};
#pragma unroll
        for (int j = 0; j < 4; j++) {
            int l0 = c * 8 + j * 2;
            if (l0 < NL + 1)     buf[l0 * XP + nn]       = (float)(ws[j] & 0xFFFFu);
            if (l0 + 1 < NL + 1) buf[(l0 + 1) * XP + nn] = (float)(ws[j] >> 16);
        }
    }
    __syncthreads();

    ull acc[4][4];
    {   // init with b1
        ulonglong2 b01 = *reinterpret_cast<const ulonglong2*>(b1 + tf * 8);
        ulonglong2 b23 = *reinterpret_cast<const ulonglong2*>(b1 + tf * 8 + 4);
#pragma unroll
        for (int i = 0; i < 4; i++) {
            acc[i][0] = b01.x; acc[i][1] = b01.y;
            acc[i][2] = b23.x; acc[i][3] = b23.y;
        }
    }

    // phase 1: cnt' @ EW  (51 iterations, 2-stage pipelined)
    {
        float4 xv = *reinterpret_cast<const float4*>(buf + tn * 4);
        const float* wr = EW + tf * 8;
        ulonglong2 w01 = *reinterpret_cast<const ulonglong2*>(wr);
        ulonglong2 w23 = *reinterpret_cast<const ulonglong2*>(wr + 4);
#pragma unroll 3
        for (int l = 0; l < NL; l++) {
            float4 xc = xv;
            ulonglong2 wa = w01, wb = w23;
            int ln = (l + 1 < NL) ? l + 1 : l;
            xv = *reinterpret_cast<const float4*>(buf + ln * XP + tn * 4);
            const float* wrn = EW + ln * HD + tf * 8;
            w01 = *reinterpret_cast<const ulonglong2*>(wrn);
            w23 = *reinterpret_cast<const ulonglong2*>(wrn + 4);
            ull xd[4] = {pack_dup(xc.x), pack_dup(xc.y), pack_dup(xc.z), pack_dup(xc.w)};
#pragma unroll
            for (int i = 0; i < 4; i++) {
                fma2(acc[i][0], xd[i], wa.x);
                fma2(acc[i][1], xd[i], wa.y);
                fma2(acc[i][2], xd[i], wb.x);
                fma2(acc[i][3], xd[i], wb.y);
            }
        }
    }
    __syncthreads();                  // all count reads done before As overwrite

    // phase-1 epilogue: relu -> buf[feat][node] (As)
    {
        float vals[4][8];
#pragma unroll
        for (int i = 0; i < 4; i++) {
#pragma unroll
            for (int j2 = 0; j2 < 4; j2++) {
                float2 p = unpack2(acc[i][j2]);
                vals[i][j2 * 2 + 0] = fmaxf(p.x, 0.f);
                vals[i][j2 * 2 + 1] = fmaxf(p.y, 0.f);
            }
        }
#pragma unroll
        for (int j = 0; j < 8; j++) {
            float4 v = make_float4(vals[0][j], vals[1][j], vals[2][j], vals[3][j]);
            *reinterpret_cast<float4*>(buf + (tf * 8 + j) * XP + tn * 4) = v;
        }
    }
    __syncthreads();

    // phase 2: a @ W2  (64 iterations, 2-stage pipelined)
    {
        ulonglong2 b01 = *reinterpret_cast<const ulonglong2*>(b2 + tf * 8);
        ulonglong2 b23 = *reinterpret_cast<const ulonglong2*>(b2 + tf * 8 + 4);
#pragma unroll
        for (int i = 0; i < 4; i++) {
            acc[i][0] = b01.x; acc[i][1] = b01.y;
            acc[i][2] = b23.x; acc[i][3] = b23.y;
        }
    }

    {
        float4 xv = *reinterpret_cast<const float4*>(buf + tn * 4);
        const float* wr = W2 + tf * 8;
        ulonglong2 w01 = *reinterpret_cast<const ulonglong2*>(wr);
        ulonglong2 w23 = *reinterpret_cast<const ulonglong2*>(wr + 4);
#pragma unroll 4
        for (int kk = 0; kk < HD; kk++) {
            float4 xc = xv;
            ulonglong2 wa = w01, wb = w23;
            int kn = (kk + 1 < HD) ? kk + 1 : kk;
            xv = *reinterpret_cast<const float4*>(buf + kn * XP + tn * 4);
            const float* wrn = W2 + kn * HD + tf * 8;
            w01 = *reinterpret_cast<const ulonglong2*>(wrn);
            w23 = *reinterpret_cast<const ulonglong2*>(wrn + 4);
            ull xd[4] = {pack_dup(xc.x), pack_dup(xc.y), pack_dup(xc.z), pack_dup(xc.w)};
#pragma unroll
            for (int i = 0; i < 4; i++) {
                fma2(acc[i][0], xd[i], wa.x);
                fma2(acc[i][1], xd[i], wa.y);
                fma2(acc[i][2], xd[i], wb.x);
                fma2(acc[i][3], xd[i], wb.y);
            }
        }
    }

#pragma unroll
    for (int i = 0; i < 4; i++) {
        int node = node_base + tn * 4 + i;
        if (node >= n) continue;
        float2 p0 = unpack2(acc[i][0]);
        float2 p1 = unpack2(acc[i][1]);
        float2 p2 = unpack2(acc[i][2]);
        float2 p3 = unpack2(acc[i][3]);
        float* o = out + (size_t)node * HD + tf * 8;
        *reinterpret_cast<float4*>(o) =
            make_float4(fmaxf(p0.x, 0.f), fmaxf(p0.y, 0.f),
                        fmaxf(p1.x, 0.f), fmaxf(p1.y, 0.f));
        *reinterpret_cast<float4*>(o + 4) =
            make_float4(fmaxf(p2.x, 0.f), fmaxf(p2.y, 0.f),
                        fmaxf(p3.x, 0.f), fmaxf(p3.y, 0.f));
    }
}

// ---------------- warp-cooperative edge scatter (layer1, 64-dim) -------------
template <int DIM>
__global__ void __launch_bounds__(256)
scatter_kernel(const int* __restrict__ src,
               const int* __restrict__ dst,
               const float* __restrict__ h,
               float* __restrict__ agg, int E)
{
    const int LPE = DIM / 4;
    const int EPW = 32 / LPE;
    int warp = (blockIdx.x * blockDim.x + threadIdx.x) >> 5;
    int lane = threadIdx.x & 31;
    int base = warp * 32;
    if (base >= E) return;

    int s = 0, d = 0;
    if (base + lane < E) {
        s = __ldg(&src[base + lane]);
        d = __ldg(&dst[base + lane]);
    }

    const int sub = lane / LPE;
    const int j4  = lane % LPE;
    int m = E - base; if (m > 32) m = 32;

    if (m == 32) {
#pragma unroll
        for (int j = 0; j < 32; j += EPW) {
            int eidx = j + sub;
            int es = __shfl_sync(0xFFFFFFFFu, s, eidx);
            int ed = __shfl_sync(0xFFFFFFFFu, d, eidx);
            float4 v = *reinterpret_cast<const float4*>(h + (size_t)es * DIM + j4 * 4);
            atomicAdd(reinterpret_cast<float4*>(agg + (size_t)ed * DIM + j4 * 4), v);
        }
    } else {
        for (int j = 0; j < m; j += EPW) {
            int eidx = j + sub;
            int es = __shfl_sync(0xFFFFFFFFu, s, eidx & 31);
            int ed = __shfl_sync(0xFFFFFFFFu, d, eidx & 31);
            if (eidx < m) {
                float4 v = *reinterpret_cast<const float4*>(h + (size_t)es * DIM + j4 * 4);
                atomicAdd(reinterpret_cast<float4*>(agg + (size_t)ed * DIM + j4 * 4), v);
            }
        }
    }
}

// ---------------- fused 2-layer MLP (layer1) + mean-pool (128-node tile) -----
template <int K1>
__global__ void __launch_bounds__(256, 3)
mlp2_kernel(const float* __restrict__ x1, const float* __restrict__ x2,
            const float* __restrict__ W1, const float* __restrict__ b1,
            const float* __restrict__ W2, const float* __restrict__ b2,
            const int* __restrict__ gids,
            float* __restrict__ sums, float* __restrict__ cnts, int n)
{
    __shared__ __align__(16) float buf[HD * XP];   // 33.8 KB, aliased Xs/As

    const int tid = threadIdx.x;
    const int node_base = blockIdx.x * 128;
    const int tn = tid & 31;
    const int tf = tid >> 5;

    ull acc[4][4];
    {
        ulonglong2 b01 = *reinterpret_cast<const ulonglong2*>(b1 + tf * 8);
        ulonglong2 b23 = *reinterpret_cast<const ulonglong2*>(b1 + tf * 8 + 4);
#pragma unroll
        for (int i = 0; i < 4; i++) {
            acc[i][0] = b01.x; acc[i][1] = b01.y;
            acc[i][2] = b23.x; acc[i][3] = b23.y;
        }
    }

    for (int kc = 0; kc < K1; kc += 16) {
        if (kc > 0) __syncthreads();
#pragma unroll
        for (int i = tid; i < 128 * 4; i += 256) {
            int nn = i & 127;
            int c  = i >> 7;
            int node = node_base + nn;
            float4 v = make_float4(0.f, 0.f, 0.f, 0.f);
            if (node < n) {
                v = *reinterpret_cast<const float4*>(x1 + (size_t)node * K1 + kc + c * 4);
                float4 u = *reinterpret_cast<const float4*>(x2 + (size_t)node * K1 + kc + c * 4);
                v.x += u.x; v.y += u.y; v.z += u.z; v.w += u.w;
            }
            buf[(c * 4 + 0) * XP + nn] = v.x;
            buf[(c * 4 + 1) * XP + nn] = v.y;
            buf[(c * 4 + 2) * XP + nn] = v.z;
            buf[(c * 4 + 3) * XP + nn] = v.w;
        }
        __syncthreads();

        // 16 iterations, 2-stage pipelined within the chunk
        float4 xv = *reinterpret_cast<const float4*>(buf + tn * 4);
        const float* wr = W1 + kc * HD + tf * 8;
        ulonglong2 w01 = *reinterpret_cast<const ulonglong2*>(wr);
        ulonglong2 w23 = *reinterpret_cast<const ulonglong2*>(wr + 4);
#pragma unroll
        for (int kk = 0; kk < 16; kk++) {
            float4 xc = xv;
            ulonglong2 wa = w01, wb = w23;
            int kn = (kk + 1 < 16) ? kk + 1 : kk;
            xv = *reinterpret_cast<const float4*>(buf + kn * XP + tn * 4);
            const float* wrn = W1 + (kc + kn) * HD + tf * 8;
            w01 = *reinterpret_cast<const ulonglong2*>(wrn);
            w23 = *reinterpret_cast<const ulonglong2*>(wrn + 4);
            ull xd[4] = {pack_dup(xc.x), pack_dup(xc.y), pack_dup(xc.z), pack_dup(xc.w)};
#pragma unroll
            for (int i = 0; i < 4; i++) {
                fma2(acc[i][0], xd[i], wa.x);
                fma2(acc[i][1], xd[i], wa.y);
                fma2(acc[i][2], xd[i], wb.x);
                fma2(acc[i][3], xd[i], wb.y);
            }
        }
    }
    __syncthreads();                  // Xs reads done before As overwrite

    {
        float vals[4][8];
#pragma unroll
        for (int i = 0; i < 4; i++) {
#pragma unroll
            for (int j2 = 0; j2 < 4; j2++) {
                float2 p = unpack2(acc[i][j2]);
                vals[i][j2 * 2 + 0] = fmaxf(p.x, 0.f);
                vals[i][j2 * 2 + 1] = fmaxf(p.y, 0.f);
            }
        }
#pragma unroll
        for (int j = 0; j < 8; j++) {
            float4 v = make_float4(vals[0][j], vals[1][j], vals[2][j], vals[3][j]);
            *reinterpret_cast<float4*>(buf + (tf * 8 + j) * XP + tn * 4) = v;
        }
    }
    __syncthreads();

    {
        ulonglong2 b01 = *reinterpret_cast<const ulonglong2*>(b2 + tf * 8);
        ulonglong2 b23 = *reinterpret_cast<const ulonglong2*>(b2 + tf * 8 + 4);
#pragma unroll
        for (int i = 0; i < 4; i++) {
            acc[i][0] = b01.x; acc[i][1] = b01.y;
            acc[i][2] = b23.x; acc[i][3] = b23.y;
        }
    }

    // phase 2 (64 iterations, 2-stage pipelined)
    {
        float4 xv = *reinterpret_cast<const float4*>(buf + tn * 4);
        const float* wr = W2 + tf * 8;
        ulonglong2 w01 = *reinterpret_cast<const ulonglong2*>(wr);
        ulonglong2 w23 = *reinterpret_cast<const ulonglong2*>(wr + 4);
#pragma unroll 4
        for (int kk = 0; kk < HD; kk++) {
            float4 xc = xv;
            ulonglong2 wa = w01, wb = w23;
            int kn = (kk + 1 < HD) ? kk + 1 : kk;
            xv = *reinterpret_cast<const float4*>(buf + kn * XP + tn * 4);
            const float* wrn = W2 + kn * HD + tf * 8;
            w01 = *reinterpret_cast<const ulonglong2*>(wrn);
            w23 = *reinterpret_cast<const ulonglong2*>(wrn + 4);
            ull xd[4] = {pack_dup(xc.x), pack_dup(xc.y), pack_dup(xc.z), pack_dup(xc.w)};
#pragma unroll
            for (int i = 0; i < 4; i++) {
                fma2(acc[i][0], xd[i], wa.x);
                fma2(acc[i][1], xd[i], wa.y);
                fma2(acc[i][2], xd[i], wb.x);
                fma2(acc[i][3], xd[i], wb.y);
            }
        }
    }

#pragma unroll
    for (int i = 0; i < 4; i++) {
        int node = node_base + tn * 4 + i;
        if (node >= n) continue;
        float2 p0 = unpack2(acc[i][0]);
        float2 p1 = unpack2(acc[i][1]);
        float2 p2 = unpack2(acc[i][2]);
        float2 p3 = unpack2(acc[i][3]);
        float4 ra = make_float4(fmaxf(p0.x, 0.f), fmaxf(p0.y, 0.f),
                                fmaxf(p1.x, 0.f), fmaxf(p1.y, 0.f));
        float4 rb = make_float4(fmaxf(p2.x, 0.f), fmaxf(p2.y, 0.f),
                                fmaxf(p3.x, 0.f), fmaxf(p3.y, 0.f));
        int g = gids[node];
        float* sg = sums + (size_t)g * HD + tf * 8;
        atomicAdd(reinterpret_cast<float4*>(sg),     ra);
        atomicAdd(reinterpret_cast<float4*>(sg + 4), rb);
        if (tf == 0) atomicAdd(&cnts[g], 1.0f);
    }
}

// ---------------- scorer: out[g] = relu(mean_h @ sw1 + sb1) @ sw2 + sb2 -----
__global__ void scorer_kernel(const float* __restrict__ sums,
                              const float* __restrict__ cnts,
                              const float* __restrict__ sw1,
                              const float* __restrict__ sb1,
                              const float* __restrict__ sw2,
                              const float* __restrict__ sb2,
                              float* __restrict__ out)
{
    int g = blockIdx.x;
    int f = threadIdx.x;           // 64 threads
    float cnt = fmaxf(cnts[g], 1.0f);
    float inv = 1.0f / cnt;
    float acc = sb1[f];
    const float* sg = sums + (size_t)g * HD;
    for (int k = 0; k < HD; k++) acc += (sg[k] * inv) * sw1[k * HD + f];
    float hf = fmaxf(acc, 0.f) * sw2[f];

    __shared__ float red[HD];
    red[f] = hf;
    __syncthreads();
    if (f < 32) red[f] += red[f + 32];
    __syncthreads();
    if (f < 32) {
        float v = red[f];
#pragma unroll
        for (int off = 16; off > 0; off >>= 1)
            v += __shfl_down_sync(0xFFFFFFFFu, v, off);
        if (f == 0) out[g] = v + sb2[0];
    }
}

// ---------------- launcher --------------------------------------------------
extern "C" void kernel_launch(void* const* d_in, const int* in_sizes, int n_in,
                              void* d_out, int out_size)
{
    const int*   labels = (const int*)  d_in[0];
    const int*   src    = (const int*)  d_in[1];
    const int*   dst    = (const int*)  d_in[2];
    const int*   gids   = (const int*)  d_in[3];
    const float* emb    = (const float*)d_in[4];
    const float* w1_0   = (const float*)d_in[5];
    const float* b1_0   = (const float*)d_in[6];
    const float* w2_0   = (const float*)d_in[7];
    const float* b2_0   = (const float*)d_in[8];
    const float* w1_1   = (const float*)d_in[9];
    const float* b1_1   = (const float*)d_in[10];
    const float* w2_1   = (const float*)d_in[11];
    const float* b2_1   = (const float*)d_in[12];
    const float* sw1    = (const float*)d_in[13];
    const float* sb1    = (const float*)d_in[14];
    const float* sw2    = (const float*)d_in[15];
    const float* sb2    = (const float*)d_in[16];
    float* out = (float*)d_out;

    int N = in_sizes[0];
    int E = in_sizes[1];
    int G = out_size;

    if (N > NMAX) N = NMAX;
    if (E > EMAX) E = EMAX;
    if (G > GMAX) G = GMAX;

    u32 *lcnt;
    float *EW, *h1, *ag1, *sums, *cnts;
    cudaGetSymbolAddress((void**)&lcnt, g_lcnt);
    cudaGetSymbolAddress((void**)&EW,   g_EW);
    cudaGetSymbolAddress((void**)&h1,   g_h1);
    cudaGetSymbolAddress((void**)&ag1,  g_ag1);
    cudaGetSymbolAddress((void**)&sums, g_sum);
    cudaGetSymbolAddress((void**)&cnts, g_cnt);

    const int TB = 256;
    const int NB = (N + 127) / 128;                 // MLP node tiles
    const int SB = ((E + 31) / 32 + 7) / 8;         // scatter blocks (8 warps)

    // 1. zero accumulators + seed self-label counts; EW = emb @ W1_0
    init_kernel<<<(N * HD + TB - 1) / TB, TB>>>(labels, N, G, lcnt, ag1, sums, cnts);
    ew_kernel<<<(NL * HD + TB - 1) / TB, TB>>>(emb, w1_0, EW);
    // 2. layer0: label-histogram scatter (1 x 4B atomic per edge)
    label_scatter_kernel<<<(E + TB - 1) / TB, TB>>>(src, dst, labels, lcnt, E);
    // 3. layer0 fused MLP from counts: h1 = relu(relu(cnt'@EW + b1)@W2 + b2)
    mlp0_kernel<<<NB, 256>>>(lcnt, EW, b1_0, w2_0, b2_0, h1, N);
    // 4. layer1 scatter: ag1[dst] += h1[src]  (64-dim, warp-cooperative)
    scatter_kernel<HD><<<SB, TB>>>(src, dst, h1, ag1, E);
    // 5. layer1 fused MLP + mean-pool accumulation
    mlp2_kernel<HD><<<NB, 256>>>(h1, ag1, w1_1, b1_1, w2_1, b2_1,
                                 gids, sums, cnts, N);
    // 6. scorer
    scorer_kernel<<<G, HD>>>(sums, cnts, sw1, sb1, sw2, sb2, out);
}

// round 17
// speedup vs baseline: 1.3523x; 1.0090x over previous
#include <cuda_runtime.h>
#include <cuda_bf16.h>

typedef unsigned long long ull;
typedef unsigned int u32;

// ---------------- problem constants (fixed shapes per reference) -------------
#define NMAX   50000
#define EMAX   1250000
#define GMAX   1024
#define LD     32      // label/embedding dim
#define HD     64      // hidden dim
#define NL     51      // number of labels (MAX_LABEL+1)
#define CW     32      // packed u16 count words per node (64 halves >= NL)
#define XP     132     // smem row pitch (floats)

// ---------------- device scratch (no allocation allowed) --------------------
__device__ u32   g_lcnt[NMAX * CW];  // per-node packed u16 label histograms
__device__ float g_EW  [NL * HD];    // emb @ W1_0  (51 x 64)
__device__ float g_h1 [NMAX * HD];   // layer0 output h
__device__ float g_ag1[NMAX * HD];   // layer1 aggregation
__device__ float g_sum[GMAX * HD];   // per-graph feature sums
__device__ float g_cnt[GMAX];        // per-graph node counts

// ---------------- packed f32x2 helpers (Blackwell FFMA2) --------------------
__device__ __forceinline__ void fma2(ull& acc, ull a, ull b) {
    asm("fma.rn.f32x2 %0, %1, %2, %0;" : "+l"(acc) : "l"(a), "l"(b));
}
__device__ __forceinline__ ull pack_dup(float x) {
    ull r;
    asm("mov.b64 %0, {%1, %1};" : "=l"(r) : "r"(__float_as_uint(x)));
    return r;
}
__device__ __forceinline__ float2 unpack2(ull v) {
    unsigned lo, hi;
    asm("mov.b64 {%0, %1}, %2;" : "=r"(lo), "=r"(hi) : "l"(v));
    return make_float2(__uint_as_float(lo), __uint_as_float(hi));
}

// ---------------- init: zero accumulators, seed self-label counts ------------
__global__ void init_kernel(const int* __restrict__ labels, int n, int g,
                            u32* __restrict__ lcnt,
                            float* __restrict__ ag1,
                            float* __restrict__ sums, float* __restrict__ cnts)
{
    int idx = blockIdx.x * blockDim.x + threadIdx.x;
    if (idx < n) {
        uint4 z = make_uint4(0, 0, 0, 0);
        uint4* p = reinterpret_cast<uint4*>(lcnt + (size_t)idx * CW);
#pragma unroll
        for (int w = 0; w < CW / 4; w++) p[w] = z;
        int lab = labels[idx];
        lab = lab < 0 ? 0 : (lab > NL - 1 ? NL - 1 : lab);
        lcnt[(size_t)idx * CW + (lab >> 1)] = 1u << ((lab & 1) * 16);
    }
    if (idx < n * HD) ag1[idx] = 0.f;
    if (idx < g * HD) sums[idx] = 0.f;
    if (idx < g)      cnts[idx] = 0.f;
}

// ---------------- EW = emb @ W1_0  (51 x 64, tiny) ---------------------------
__global__ void ew_kernel(const float* __restrict__ emb,
                          const float* __restrict__ W1,
                          float* __restrict__ EW)
{
    int idx = blockIdx.x * blockDim.x + threadIdx.x;
    if (idx >= NL * HD) return;
    int l = idx / HD, f = idx % HD;
    float s = 0.f;
#pragma unroll
    for (int k = 0; k < LD; k++) s += emb[l * LD + k] * W1[k * HD + f];
    EW[idx] = s;
}

// ---------------- layer0 edge pass: label histogram scatter ------------------
__global__ void __launch_bounds__(256)
label_scatter_kernel(const int* __restrict__ src, const int* __restrict__ dst,
                     const int* __restrict__ labels, u32* __restrict__ lcnt, int E)
{
    int e = blockIdx.x * blockDim.x + threadIdx.x;
    if (e >= E) return;
    int s = __ldg(&src[e]);
    int d = __ldg(&dst[e]);
    int lab = __ldg(&labels[s]);
    lab = lab < 0 ? 0 : (lab > NL - 1 ? NL - 1 : lab);
    atomicAdd(&lcnt[(size_t)d * CW + (lab >> 1)], 1u << ((lab & 1) * 16));
}

// ---------------- layer0 fused MLP from label counts (128-node tile) ---------
// phase 1: a = relu(b1 + cnt' @ EW)   phase 2: h1 = relu(a @ W2 + b2)
// 256 threads; thread = 4 nodes x 8 feats (feature-pair FFMA2 accumulators).
// Hot loops software-pipelined: prefetch iter l+1's X/W while computing iter l.
__global__ void __launch_bounds__(256, 3)
mlp0_kernel(const u32* __restrict__ lcnt,
            const float* __restrict__ EW, const float* __restrict__ b1,
            const float* __restrict__ W2, const float* __restrict__ b2,
            float* __restrict__ out, int n)
{
    __shared__ __align__(16) float buf[HD * XP];   // 33.8 KB, aliased Cs/As

    const int tid = threadIdx.x;
    const int node_base = blockIdx.x * 128;
    const int tn = tid & 31;          // node group: 4 lane-contiguous nodes
    const int tf = tid >> 5;          // feature group: 8 feats = 4 f32x2

    // stage counts -> buf[label][node] as floats
#pragma unroll
    for (int i = tid; i < 128 * 7; i += 256) {
        int nn = i & 127;
        int c  = i >> 7;              // word group 0..6 -> labels c*8 .. c*8+7
        int node = node_base + nn;
        uint4 w = make_uint4(0, 0, 0, 0);
        if (node < n)
            w = *reinterpret_cast<const uint4*>(lcnt + (size_t)node * CW + c * 4);
        u32 ws[4] = {w.x, w.y, w.z, w.w};
#pragma unroll
        for (int j = 0; j < 4; j++) {
            int l0 = c * 8 + j * 2;
            if (l0 < NL + 1)     buf[l0 * XP + nn]       = (float)(ws[j] & 0xFFFFu);
            if (l0 + 1 < NL + 1) buf[(l0 + 1) * XP + nn] = (float)(ws[j] >> 16);
        }
    }
    __syncthreads();

    ull acc[4][4];
    {   // init with b1
        ulonglong2 b01 = *reinterpret_cast<const ulonglong2*>(b1 + tf * 8);
        ulonglong2 b23 = *reinterpret_cast<const ulonglong2*>(b1 + tf * 8 + 4);
#pragma unroll
        for (int i = 0; i < 4; i++) {
            acc[i][0] = b01.x; acc[i][1] = b01.y;
            acc[i][2] = b23.x; acc[i][3] = b23.y;
        }
    }

    // phase 1: cnt' @ EW  (51 iterations, 2-stage pipelined)
    {
        float4 xv = *reinterpret_cast<const float4*>(buf + tn * 4);
        const float* wr = EW + tf * 8;
        ulonglong2 w01 = *reinterpret_cast<const ulonglong2*>(wr);
        ulonglong2 w23 = *reinterpret_cast<const ulonglong2*>(wr + 4);
#pragma unroll 3
        for (int l = 0; l < NL; l++) {
            float4 xc = xv;
            ulonglong2 wa = w01, wb = w23;
            int ln = (l + 1 < NL) ? l + 1 : l;
            xv = *reinterpret_cast<const float4*>(buf + ln * XP + tn * 4);
            const float* wrn = EW + ln * HD + tf * 8;
            w01 = *reinterpret_cast<const ulonglong2*>(wrn);
            w23 = *reinterpret_cast<const ulonglong2*>(wrn + 4);
            ull xd[4] = {pack_dup(xc.x), pack_dup(xc.y), pack_dup(xc.z), pack_dup(xc.w)};
#pragma unroll
            for (int i = 0; i < 4; i++) {
                fma2(acc[i][0], xd[i], wa.x);
                fma2(acc[i][1], xd[i], wa.y);
                fma2(acc[i][2], xd[i], wb.x);
                fma2(acc[i][3], xd[i], wb.y);
            }
        }
    }
    __syncthreads();                  // all count reads done before As overwrite

    // phase-1 epilogue: relu -> buf[feat][node] (As)
    {
        float vals[4][8];
#pragma unroll
        for (int i = 0; i < 4; i++) {
#pragma unroll
            for (int j2 = 0; j2 < 4; j2++) {
                float2 p = unpack2(acc[i][j2]);
                vals[i][j2 * 2 + 0] = fmaxf(p.x, 0.f);
                vals[i][j2 * 2 + 1] = fmaxf(p.y, 0.f);
            }
        }
#pragma unroll
        for (int j = 0; j < 8; j++) {
            float4 v = make_float4(vals[0][j], vals[1][j], vals[2][j], vals[3][j]);
            *reinterpret_cast<float4*>(buf + (tf * 8 + j) * XP + tn * 4) = v;
        }
    }
    __syncthreads();

    // phase 2: a @ W2  (64 iterations, 2-stage pipelined)
    {
        ulonglong2 b01 = *reinterpret_cast<const ulonglong2*>(b2 + tf * 8);
        ulonglong2 b23 = *reinterpret_cast<const ulonglong2*>(b2 + tf * 8 + 4);
#pragma unroll
        for (int i = 0; i < 4; i++) {
            acc[i][0] = b01.x; acc[i][1] = b01.y;
            acc[i][2] = b23.x; acc[i][3] = b23.y;
        }
    }

    {
        float4 xv = *reinterpret_cast<const float4*>(buf + tn * 4);
        const float* wr = W2 + tf * 8;
        ulonglong2 w01 = *reinterpret_cast<const ulonglong2*>(wr);
        ulonglong2 w23 = *reinterpret_cast<const ulonglong2*>(wr + 4);
#pragma unroll 4
        for (int kk = 0; kk < HD; kk++) {
            float4 xc = xv;
            ulonglong2 wa = w01, wb = w23;
            int kn = (kk + 1 < HD) ? kk + 1 : kk;
            xv = *reinterpret_cast<const float4*>(buf + kn * XP + tn * 4);
            const float* wrn = W2 + kn * HD + tf * 8;
            w01 = *reinterpret_cast<const ulonglong2*>(wrn);
            w23 = *reinterpret_cast<const ulonglong2*>(wrn + 4);
            ull xd[4] = {pack_dup(xc.x), pack_dup(xc.y), pack_dup(xc.z), pack_dup(xc.w)};
#pragma unroll
            for (int i = 0; i < 4; i++) {
                fma2(acc[i][0], xd[i], wa.x);
                fma2(acc[i][1], xd[i], wa.y);
                fma2(acc[i][2], xd[i], wb.x);
                fma2(acc[i][3], xd[i], wb.y);
            }
        }
    }

#pragma unroll
    for (int i = 0; i < 4; i++) {
        int node = node_base + tn * 4 + i;
        if (node >= n) continue;
        float2 p0 = unpack2(acc[i][0]);
        float2 p1 = unpack2(acc[i][1]);
        float2 p2 = unpack2(acc[i][2]);
        float2 p3 = unpack2(acc[i][3]);
        float* o = out + (size_t)node * HD + tf * 8;
        *reinterpret_cast<float4*>(o) =
            make_float4(fmaxf(p0.x, 0.f), fmaxf(p0.y, 0.f),
                        fmaxf(p1.x, 0.f), fmaxf(p1.y, 0.f));
        *reinterpret_cast<float4*>(o + 4) =
            make_float4(fmaxf(p2.x, 0.f), fmaxf(p2.y, 0.f),
                        fmaxf(p3.x, 0.f), fmaxf(p3.y, 0.f));
    }
}

// ---------------- warp-cooperative edge scatter (layer1, 64-dim) -------------
template <int DIM>
__global__ void __launch_bounds__(256)
scatter_kernel(const int* __restrict__ src,
               const int* __restrict__ dst,
               const float* __restrict__ h,
               float* __restrict__ agg, int E)
{
    const int LPE = DIM / 4;
    const int EPW = 32 / LPE;
    int warp = (blockIdx.x * blockDim.x + threadIdx.x) >> 5;
    int lane = threadIdx.x & 31;
    int base = warp * 32;
    if (base >= E) return;

    int s = 0, d = 0;
    if (base + lane < E) {
        s = __ldg(&src[base + lane]);
        d = __ldg(&dst[base + lane]);
    }

    const int sub = lane / LPE;
    const int j4  = lane % LPE;
    int m = E - base; if (m > 32) m = 32;

    if (m == 32) {
#pragma unroll
        for (int j = 0; j < 32; j += EPW) {
            int eidx = j + sub;
            int es = __shfl_sync(0xFFFFFFFFu, s, eidx);
            int ed = __shfl_sync(0xFFFFFFFFu, d, eidx);
            float4 v = *reinterpret_cast<const float4*>(h + (size_t)es * DIM + j4 * 4);
            atomicAdd(reinterpret_cast<float4*>(agg + (size_t)ed * DIM + j4 * 4), v);
        }
    } else {
        for (int j = 0; j < m; j += EPW) {
            int eidx = j + sub;
            int es = __shfl_sync(0xFFFFFFFFu, s, eidx & 31);
            int ed = __shfl_sync(0xFFFFFFFFu, d, eidx & 31);
            if (eidx < m) {
                float4 v = *reinterpret_cast<const float4*>(h + (size_t)es * DIM + j4 * 4);
                atomicAdd(reinterpret_cast<float4*>(agg + (size_t)ed * DIM + j4 * 4), v);
            }
        }
    }
}

// ---------------- fused 2-layer MLP (layer1) + mean-pool (128-node tile) -----
template <int K1>
__global__ void __launch_bounds__(256, 3)
mlp2_kernel(const float* __restrict__ x1, const float* __restrict__ x2,
            const float* __restrict__ W1, const float* __restrict__ b1,
            const float* __restrict__ W2, const float* __restrict__ b2,
            const int* __restrict__ gids,
            float* __restrict__ sums, float* __restrict__ cnts, int n)
{
    __shared__ __align__(16) float buf[HD * XP];   // 33.8 KB, aliased Xs/As

    const int tid = threadIdx.x;
    const int node_base = blockIdx.x * 128;
    const int tn = tid & 31;
    const int tf = tid >> 5;

    ull acc[4][4];
    {
        ulonglong2 b01 = *reinterpret_cast<const ulonglong2*>(b1 + tf * 8);
        ulonglong2 b23 = *reinterpret_cast<const ulonglong2*>(b1 + tf * 8 + 4);
#pragma unroll
        for (int i = 0; i < 4; i++) {
            acc[i][0] = b01.x; acc[i][1] = b01.y;
            acc[i][2] = b23.x; acc[i][3] = b23.y;
        }
    }

    for (int kc = 0; kc < K1; kc += 16) {
        if (kc > 0) __syncthreads();
#pragma unroll
        for (int i = tid; i < 128 * 4; i += 256) {
            int nn = i & 127;
            int c  = i >> 7;
            int node = node_base + nn;
            float4 v = make_float4(0.f, 0.f, 0.f, 0.f);
            if (node < n) {
                v = *reinterpret_cast<const float4*>(x1 + (size_t)node * K1 + kc + c * 4);
                float4 u = *reinterpret_cast<const float4*>(x2 + (size_t)node * K1 + kc + c * 4);
                v.x += u.x; v.y += u.y; v.z += u.z; v.w += u.w;
            }
            buf[(c * 4 + 0) * XP + nn] = v.x;
            buf[(c * 4 + 1) * XP + nn] = v.y;
            buf[(c * 4 + 2) * XP + nn] = v.z;
            buf[(c * 4 + 3) * XP + nn] = v.w;
        }
        __syncthreads();

        // 16 iterations, 2-stage pipelined within the chunk
        float4 xv = *reinterpret_cast<const float4*>(buf + tn * 4);
        const float* wr = W1 + kc * HD + tf * 8;
        ulonglong2 w01 = *reinterpret_cast<const ulonglong2*>(wr);
        ulonglong2 w23 = *reinterpret_cast<const ulonglong2*>(wr + 4);
#pragma unroll
        for (int kk = 0; kk < 16; kk++) {
            float4 xc = xv;
            ulonglong2 wa = w01, wb = w23;
            int kn = (kk + 1 < 16) ? kk + 1 : kk;
            xv = *reinterpret_cast<const float4*>(buf + kn * XP + tn * 4);
            const float* wrn = W1 + (kc + kn) * HD + tf * 8;
            w01 = *reinterpret_cast<const ulonglong2*>(wrn);
            w23 = *reinterpret_cast<const ulonglong2*>(wrn + 4);
            ull xd[4] = {pack_dup(xc.x), pack_dup(xc.y), pack_dup(xc.z), pack_dup(xc.w)};
#pragma unroll
            for (int i = 0; i < 4; i++) {
                fma2(acc[i][0], xd[i], wa.x);
                fma2(acc[i][1], xd[i], wa.y);
                fma2(acc[i][2], xd[i], wb.x);
                fma2(acc[i][3], xd[i], wb.y);
            }
        }
    }
    __syncthreads();                  // Xs reads done before As overwrite

    {
        float vals[4][8];
#pragma unroll
        for (int i = 0; i < 4; i++) {
#pragma unroll
            for (int j2 = 0; j2 < 4; j2++) {
                float2 p = unpack2(acc[i][j2]);
                vals[i][j2 * 2 + 0] = fmaxf(p.x, 0.f);
                vals[i][j2 * 2 + 1] = fmaxf(p.y, 0.f);
            }
        }
#pragma unroll
        for (int j = 0; j < 8; j++) {
            float4 v = make_float4(vals[0][j], vals[1][j], vals[2][j], vals[3][j]);
            *reinterpret_cast<float4*>(buf + (tf * 8 + j) * XP + tn * 4) = v;
        }
    }
    __syncthreads();

    {
        ulonglong2 b01 = *reinterpret_cast<const ulonglong2*>(b2 + tf * 8);
        ulonglong2 b23 = *reinterpret_cast<const ulonglong2*>(b2 + tf * 8 + 4);
#pragma unroll
        for (int i = 0; i < 4; i++) {
            acc[i][0] = b01.x; acc[i][1] = b01.y;
            acc[i][2] = b23.x; acc[i][3] = b23.y;
        }
    }

    // phase 2 (64 iterations, 2-stage pipelined)
    {
        float4 xv = *reinterpret_cast<const float4*>(buf + tn * 4);
        const float* wr = W2 + tf * 8;
        ulonglong2 w01 = *reinterpret_cast<const ulonglong2*>(wr);
        ulonglong2 w23 = *reinterpret_cast<const ulonglong2*>(wr + 4);
#pragma unroll 4
        for (int kk = 0; kk < HD; kk++) {
            float4 xc = xv;
            ulonglong2 wa = w01, wb = w23;
            int kn = (kk + 1 < HD) ? kk + 1 : kk;
            xv = *reinterpret_cast<const float4*>(buf + kn * XP + tn * 4);
            const float* wrn = W2 + kn * HD + tf * 8;
            w01 = *reinterpret_cast<const ulonglong2*>(wrn);
            w23 = *reinterpret_cast<const ulonglong2*>(wrn + 4);
            ull xd[4] = {pack_dup(xc.x), pack_dup(xc.y), pack_dup(xc.z), pack_dup(xc.w)};
#pragma unroll
            for (int i = 0; i < 4; i++) {
                fma2(acc[i][0], xd[i], wa.x);
                fma2(acc[i][1], xd[i], wa.y);
                fma2(acc[i][2], xd[i], wb.x);
                fma2(acc[i][3], xd[i], wb.y);
            }
        }
    }

#pragma unroll
    for (int i = 0; i < 4; i++) {
        int node = node_base + tn * 4 + i;
        if (node >= n) continue;
        float2 p0 = unpack2(acc[i][0]);
        float2 p1 = unpack2(acc[i][1]);
        float2 p2 = unpack2(acc[i][2]);
        float2 p3 = unpack2(acc[i][3]);
        float4 ra = make_float4(fmaxf(p0.x, 0.f), fmaxf(p0.y, 0.f),
                                fmaxf(p1.x, 0.f), fmaxf(p1.y, 0.f));
        float4 rb = make_float4(fmaxf(p2.x, 0.f), fmaxf(p2.y, 0.f),
                                fmaxf(p3.x, 0.f), fmaxf(p3.y, 0.f));
        int g = gids[node];
        float* sg = sums + (size_t)g * HD + tf * 8;
        atomicAdd(reinterpret_cast<float4*>(sg),     ra);
        atomicAdd(reinterpret_cast<float4*>(sg + 4), rb);
        if (tf == 0) atomicAdd(&cnts[g], 1.0f);
    }
}

// ---------------- scorer: out[g] = relu(mean_h @ sw1 + sb1) @ sw2 + sb2 -----
__global__ void scorer_kernel(const float* __restrict__ sums,
                              const float* __restrict__ cnts,
                              const float* __restrict__ sw1,
                              const float* __restrict__ sb1,
                              const float* __restrict__ sw2,
                              const float* __restrict__ sb2,
                              float* __restrict__ out)
{
    int g = blockIdx.x;
    int f = threadIdx.x;           // 64 threads
    float cnt = fmaxf(cnts[g], 1.0f);
    float inv = 1.0f / cnt;
    float acc = sb1[f];
    const float* sg = sums + (size_t)g * HD;
    for (int k = 0; k < HD; k++) acc += (sg[k] * inv) * sw1[k * HD + f];
    float hf = fmaxf(acc, 0.f) * sw2[f];

    __shared__ float red[HD];
    red[f] = hf;
    __syncthreads();
    if (f < 32) red[f] += red[f + 32];
    __syncthreads();
    if (f < 32) {
        float v = red[f];
#pragma unroll
        for (int off = 16; off > 0; off >>= 1)
            v += __shfl_down_sync(0xFFFFFFFFu, v, off);
        if (f == 0) out[g] = v + sb2[0];
    }
}

// ---------------- launcher --------------------------------------------------
extern "C" void kernel_launch(void* const* d_in, const int* in_sizes, int n_in,
                              void* d_out, int out_size)
{
    const int*   labels = (const int*)  d_in[0];
    const int*   src    = (const int*)  d_in[1];
    const int*   dst    = (const int*)  d_in[2];
    const int*   gids   = (const int*)  d_in[3];
    const float* emb    = (const float*)d_in[4];
    const float* w1_0   = (const float*)d_in[5];
    const float* b1_0   = (const float*)d_in[6];
    const float* w2_0   = (const float*)d_in[7];
    const float* b2_0   = (const float*)d_in[8];
    const float* w1_1   = (const float*)d_in[9];
    const float* b1_1   = (const float*)d_in[10];
    const float* w2_1   = (const float*)d_in[11];
    const float* b2_1   = (const float*)d_in[12];
    const float* sw1    = (const float*)d_in[13];
    const float* sb1    = (const float*)d_in[14];
    const float* sw2    = (const float*)d_in[15];
    const float* sb2    = (const float*)d_in[16];
    float* out = (float*)d_out;

    int N = in_sizes[0];
    int E = in_sizes[1];
    int G = out_size;

    if (N > NMAX) N = NMAX;
    if (E > EMAX) E = EMAX;
    if (G > GMAX) G = GMAX;

    u32 *lcnt;
    float *EW, *h1, *ag1, *sums, *cnts;
    cudaGetSymbolAddress((void**)&lcnt, g_lcnt);
    cudaGetSymbolAddress((void**)&EW,   g_EW);
    cudaGetSymbolAddress((void**)&h1,   g_h1);
    cudaGetSymbolAddress((void**)&ag1,  g_ag1);
    cudaGetSymbolAddress((void**)&sums, g_sum);
    cudaGetSymbolAddress((void**)&cnts, g_cnt);

    const int TB = 256;
    const int NB = (N + 127) / 128;                 // MLP node tiles
    const int SB = ((E + 31) / 32 + 7) / 8;         // scatter blocks (8 warps)

    // 1. zero accumulators + seed self-label counts; EW = emb @ W1_0
    init_kernel<<<(N * HD + TB - 1) / TB, TB>>>(labels, N, G, lcnt, ag1, sums, cnts);
    ew_kernel<<<(NL * HD + TB - 1) / TB, TB>>>(emb, w1_0, EW);
    // 2. layer0: label-histogram scatter (1 x 4B atomic per edge)
    label_scatter_kernel<<<(E + TB - 1) / TB, TB>>>(src, dst, labels, lcnt, E);
    // 3. layer0 fused MLP from counts: h1 = relu(relu(cnt'@EW + b1)@W2 + b2)
    mlp0_kernel<<<NB, 256>>>(lcnt, EW, b1_0, w2_0, b2_0, h1, N);
    // 4. layer1 scatter: ag1[dst] += h1[src]  (64-dim, warp-cooperative)
    scatter_kernel<HD><<<SB, TB>>>(src, dst, h1, ag1, E);
    // 5. layer1 fused MLP + mean-pool accumulation
    mlp2_kernel<HD><<<NB, 256>>>(h1, ag1, w1_1, b1_1, w2_1, b2_1,
                                 gids, sums, cnts, N);
    // 6. scorer
    scorer_kernel<<<G, HD>>>(sums, cnts, sw1, sb1, sw2, sb2, out);
}